// round 7
// baseline (speedup 1.0000x reference)
#include <cuda_runtime.h>
#include <cuda_bf16.h>
#include <math.h>
#include <stdint.h>

#define NN 100000
#define GG 6000
#define EE 400000

// ---------------- scratch (static __device__ — no allocs allowed) ----------------
__device__ float g_q  [NN * 128];
__device__ float g_k  [GG * 128];
__device__ float g_val[GG * 128];
__device__ float g_ms [NN * 128];
__device__ float g_mv [NN * 384];
__device__ float g_t0 [NN * 128];
__device__ float g_t4 [NN * 128];
__device__ float g_t5 [NN * 128];
__device__ float g_v1 [NN * 384];
__device__ float g_v2 [NN * 384];
__device__ float g_Pp [GG * 512];
__device__ float g_Ps [GG * 512];
// pre-converted weights: bf16 hi/lo, B-layout [n][k] blocked-atom SW128, packed u32
__device__ uint32_t g_whi[9 * 8192];
__device__ uint32_t g_wlo[9 * 8192];

__device__ __forceinline__ float silu_f(float x) {
    return x / (1.0f + __expf(-x));
}

// blocked-atom SW128 byte offset for a [128 rows][128 cols bf16] tile
__device__ __forceinline__ uint32_t blk_off(int row, int col) {
    uint32_t off = (uint32_t)((row >> 3) + (col >> 6) * 16) * 1024u
                 + (uint32_t)(row & 7) * 128u + (uint32_t)(col & 63) * 2u;
    return off ^ ((off >> 3) & 0x70);
}

// ---------------- weight conversion: W[k][n] fp32 -> B[n][k] bf16 hi/lo ----------------
__global__ void wconv_kernel(
    const float* __restrict__ W0, const float* __restrict__ W1,
    const float* __restrict__ W2, const float* __restrict__ W3,
    const float* __restrict__ W4, const float* __restrict__ W5,
    const float* __restrict__ W6, const float* __restrict__ W7,
    const float* __restrict__ W8)
{
    const float* Ws[9] = {W0, W1, W2, W3, W4, W5, W6, W7, W8};
    int gidx = blockIdx.x * 256 + threadIdx.x;
    if (gidx >= 9 * 8192) return;
    int w = gidx >> 13, p = gidx & 8191;
    int n = p >> 6, k2 = (p & 63) * 2;
    const float* W = Ws[w];
    float x0 = W[k2 * 128 + n], x1 = W[(k2 + 1) * 128 + n];
    __nv_bfloat16 h0 = __float2bfloat16(x0), h1 = __float2bfloat16(x1);
    float r0 = x0 - __bfloat162float(h0), r1 = x1 - __bfloat162float(h1);
    __nv_bfloat16 l0 = __float2bfloat16(r0), l1 = __float2bfloat16(r1);
    uint32_t o = blk_off(n, k2) >> 2;
    g_whi[w * 8192 + o] = (uint32_t)__bfloat16_as_ushort(h0)
                        | ((uint32_t)__bfloat16_as_ushort(h1) << 16);
    g_wlo[w * 8192 + o] = (uint32_t)__bfloat16_as_ushort(l0)
                        | ((uint32_t)__bfloat16_as_ushort(l1) << 16);
}

// ---------------- arch-specific PTX helpers (guarded) ----------------
#if defined(__CUDA_ARCH_FEAT_SM103_ALL) || !defined(__CUDA_ARCH__)
#define HAVE_TCGEN05 1
#else
#define HAVE_TCGEN05 0
#endif

__device__ __forceinline__ uint32_t smem_u32(const void* p) {
    uint32_t a;
    asm("{ .reg .u64 t; cvta.to.shared.u64 t, %1; cvt.u32.u64 %0, t; }"
        : "=r"(a) : "l"(p));
    return a;
}

#if HAVE_TCGEN05
__device__ __forceinline__ uint32_t elect1() {
    uint32_t p;
    asm volatile("{\n\t.reg .pred p;\n\telect.sync _|p, 0xFFFFFFFF;\n\t"
                 "selp.b32 %0, 1, 0, p;\n\t}" : "=r"(p));
    return p;
}
__device__ __forceinline__ void mma_f16_ss(uint32_t d, uint64_t a, uint64_t b,
                                           uint32_t idesc, uint32_t en) {
    asm volatile("{\n\t.reg .pred p;\n\tsetp.ne.u32 p, %5, 0;\n\t"
                 "tcgen05.mma.cta_group::1.kind::f16 [%0], %1, %2, %3, {%4,%4,%4,%4}, p;\n\t}"
                 :: "r"(d), "l"(a), "l"(b), "r"(idesc), "r"(0u), "r"(en) : "memory");
}
__device__ __forceinline__ void mbar_wait(uint32_t mbar, uint32_t parity) {
    uint32_t done;
    asm volatile("{\n\t.reg .pred p;\n\t"
                 "mbarrier.try_wait.parity.acquire.cta.shared::cta.b64 p, [%1], %2;\n\t"
                 "selp.b32 %0, 1, 0, p;\n\t}"
                 : "=r"(done) : "r"(mbar), "r"(parity) : "memory");
    if (!done) {
        asm volatile("{\n\t.reg .pred P1;\n\t"
                     "WAIT_LOOP_%=:\n\t"
                     "mbarrier.try_wait.parity.acquire.cta.shared::cta.b64 P1, [%0], %1, 0x989680;\n\t"
                     "@P1 bra.uni WAIT_DONE_%=;\n\t"
                     "bra.uni WAIT_LOOP_%=;\n\t"
                     "WAIT_DONE_%=:\n\t}"
                     :: "r"(mbar), "r"(parity) : "memory");
    }
}
#define LDTM_X32(r, addr) \
    asm volatile( \
        "tcgen05.ld.sync.aligned.32x32b.x32.b32 " \
        "{%0, %1, %2, %3, %4, %5, %6, %7, " \
        " %8, %9, %10, %11, %12, %13, %14, %15, " \
        " %16, %17, %18, %19, %20, %21, %22, %23, " \
        " %24, %25, %26, %27, %28, %29, %30, %31}, [%32];" \
        : "=r"((r)[0]),  "=r"((r)[1]),  "=r"((r)[2]),  "=r"((r)[3]), \
          "=r"((r)[4]),  "=r"((r)[5]),  "=r"((r)[6]),  "=r"((r)[7]), \
          "=r"((r)[8]),  "=r"((r)[9]),  "=r"((r)[10]), "=r"((r)[11]), \
          "=r"((r)[12]), "=r"((r)[13]), "=r"((r)[14]), "=r"((r)[15]), \
          "=r"((r)[16]), "=r"((r)[17]), "=r"((r)[18]), "=r"((r)[19]), \
          "=r"((r)[20]), "=r"((r)[21]), "=r"((r)[22]), "=r"((r)[23]), \
          "=r"((r)[24]), "=r"((r)[25]), "=r"((r)[26]), "=r"((r)[27]), \
          "=r"((r)[28]), "=r"((r)[29]), "=r"((r)[30]), "=r"((r)[31]) \
        : "r"(addr))
#endif  // HAVE_TCGEN05

// ---------------- pipelined tcgen05 GEMM: up to 3 weights, TMEM ping-pong ----------------
// mode 0: C = A@W (+bias). mode 1: C = g_mv + g_t0[row/3] * (A@W)   (dv fusion)
#define SM_TMEM 0
#define SM_MB0  8
#define SM_MB1  16
#define SM_MB2  24
#define SM_AHI  1024
#define SM_ALO  33792
#define SM_B0HI 66560
#define SM_B0LO 99328
#define SM_B1HI 132096
#define SM_B1LO 164864
#define TC_SMEM 197632
#define TMEM_COLS 512

#if HAVE_TCGEN05
__device__ __forceinline__ void tc_copyB(char* smem, uint32_t dsthi, uint32_t dstlo,
                                         int w, int tid)
{
    const uint4* shi = (const uint4*)(g_whi + w * 8192);
    const uint4* slo = (const uint4*)(g_wlo + w * 8192);
    uint4* dhi = (uint4*)(smem + dsthi);
    uint4* dlo = (uint4*)(smem + dstlo);
    for (int i = tid; i < 2048; i += 256) { dhi[i] = shi[i]; dlo[i] = slo[i]; }
}

__device__ __forceinline__ void tc_issue_mma(uint32_t tmem_d, uint64_t ahi, uint64_t alo,
                                             uint64_t bhi, uint64_t blo, uint32_t mbar)
{
    const uint32_t IDESC = (1u << 4) | (1u << 7) | (1u << 10) | (16u << 17) | (8u << 24);
    uint32_t en = 0;
    #pragma unroll
    for (int kc = 0; kc < 8; kc++) {
        uint64_t ko = (uint64_t)((kc & 3) * 2 + (kc >> 2) * 1024);
        mma_f16_ss(tmem_d, ahi + ko, bhi + ko, IDESC, en); en = 1;
    }
    #pragma unroll
    for (int kc = 0; kc < 8; kc++) {
        uint64_t ko = (uint64_t)((kc & 3) * 2 + (kc >> 2) * 1024);
        mma_f16_ss(tmem_d, ahi + ko, blo + ko, IDESC, 1);
    }
    #pragma unroll
    for (int kc = 0; kc < 8; kc++) {
        uint64_t ko = (uint64_t)((kc & 3) * 2 + (kc >> 2) * 1024);
        mma_f16_ss(tmem_d, alo + ko, bhi + ko, IDESC, 1);
    }
    asm volatile("tcgen05.commit.cta_group::1.mbarrier::arrive::one.shared::cluster.b64 [%0];"
                 :: "r"(mbar) : "memory");
}

__device__ __forceinline__ void tc_epilogue(uint32_t tmem_d, int M, int row0,
                                            int wid, int lane, int mode,
                                            const float* bias, float* C)
{
    if (wid >= 4) return;
    int gr = row0 + wid * 32 + lane;
    #pragma unroll 1
    for (int cb = 0; cb < 4; cb++) {
        uint32_t d[32];
        LDTM_X32(d, tmem_d + cb * 32);
        asm volatile("tcgen05.wait::ld.sync.aligned;" ::: "memory");
        if (gr < M) {
            float* dst = C + (size_t)gr * 128 + cb * 32;
            if (mode == 1) {
                const float4* mvp = (const float4*)(g_mv + (size_t)gr * 128 + cb * 32);
                const float4* t0p = (const float4*)(g_t0 + (size_t)(gr / 3) * 128 + cb * 32);
                #pragma unroll
                for (int q = 0; q < 8; q++) {
                    float4 mv = mvp[q], t0 = t0p[q];
                    float4 o;
                    o.x = mv.x + t0.x * __uint_as_float(d[q * 4 + 0]);
                    o.y = mv.y + t0.y * __uint_as_float(d[q * 4 + 1]);
                    o.z = mv.z + t0.z * __uint_as_float(d[q * 4 + 2]);
                    o.w = mv.w + t0.w * __uint_as_float(d[q * 4 + 3]);
                    ((float4*)dst)[q] = o;
                }
            } else {
                #pragma unroll
                for (int q = 0; q < 8; q++) {
                    float4 o;
                    o.x = __uint_as_float(d[q * 4 + 0]);
                    o.y = __uint_as_float(d[q * 4 + 1]);
                    o.z = __uint_as_float(d[q * 4 + 2]);
                    o.w = __uint_as_float(d[q * 4 + 3]);
                    if (bias) {
                        const float* bb = bias + cb * 32 + q * 4;
                        o.x += bb[0]; o.y += bb[1]; o.z += bb[2]; o.w += bb[3];
                    }
                    ((float4*)dst)[q] = o;
                }
            }
        }
    }
}
#endif  // HAVE_TCGEN05

__global__ __launch_bounds__(256, 1) __cluster_dims__(1, 1, 1)
void tc_gemm(const float* __restrict__ A, int M,
             int w0, int m0, const float* __restrict__ W0f, const float* __restrict__ b0, float* __restrict__ C0,
             int w1, int m1, const float* __restrict__ W1f, const float* __restrict__ b1, float* __restrict__ C1,
             int w2, int m2, const float* __restrict__ W2f, const float* __restrict__ b2, float* __restrict__ C2)
{
#if HAVE_TCGEN05
    extern __shared__ char smem[];
    uint32_t sb = smem_u32(smem);
    int tid = threadIdx.x, wid = tid >> 5, lane = tid & 31;
    int row0 = blockIdx.x * 128;

    if (wid == 0)
        asm volatile("tcgen05.alloc.cta_group::1.sync.aligned.shared::cta.b32 [%0], %1;"
                     :: "r"(sb + SM_TMEM), "r"((uint32_t)TMEM_COLS) : "memory");
    if (tid == 0) {
        asm volatile("mbarrier.init.shared.b64 [%0], 1;" :: "r"(sb + SM_MB0) : "memory");
        asm volatile("mbarrier.init.shared.b64 [%0], 1;" :: "r"(sb + SM_MB1) : "memory");
        asm volatile("mbarrier.init.shared.b64 [%0], 1;" :: "r"(sb + SM_MB2) : "memory");
    }
    __syncthreads();
    uint32_t tmem;
    asm volatile("ld.shared.b32 %0, [%1];" : "=r"(tmem) : "r"(sb + SM_TMEM));

    // stage A tile as bf16 hi/lo into blocked-atom SW128 SMEM
    for (int p = tid; p < 8192; p += 256) {
        int r = p >> 6, k2 = (p & 63) * 2;
        float2 x = make_float2(0.f, 0.f);
        if (row0 + r < M) x = *(const float2*)(A + (size_t)(row0 + r) * 128 + k2);
        __nv_bfloat16 h0 = __float2bfloat16(x.x), h1 = __float2bfloat16(x.y);
        float r0f = x.x - __bfloat162float(h0), r1f = x.y - __bfloat162float(h1);
        __nv_bfloat16 l0 = __float2bfloat16(r0f), l1 = __float2bfloat16(r1f);
        uint32_t hiw = (uint32_t)__bfloat16_as_ushort(h0)
                     | ((uint32_t)__bfloat16_as_ushort(h1) << 16);
        uint32_t low = (uint32_t)__bfloat16_as_ushort(l0)
                     | ((uint32_t)__bfloat16_as_ushort(l1) << 16);
        uint32_t off = blk_off(r, k2);
        *(uint32_t*)(smem + SM_AHI + off) = hiw;
        *(uint32_t*)(smem + SM_ALO + off) = low;
    }

    const uint64_t DESCB = (2ull << 61) | (1ull << 46) | (64ull << 32) | (1ull << 16);
    uint64_t ahi  = DESCB | ((uint64_t)((sb + SM_AHI)  >> 4) & 0x3FFF);
    uint64_t alo  = DESCB | ((uint64_t)((sb + SM_ALO)  >> 4) & 0x3FFF);
    uint64_t b0hi = DESCB | ((uint64_t)((sb + SM_B0HI) >> 4) & 0x3FFF);
    uint64_t b0lo = DESCB | ((uint64_t)((sb + SM_B0LO) >> 4) & 0x3FFF);
    uint64_t b1hi = DESCB | ((uint64_t)((sb + SM_B1HI) >> 4) & 0x3FFF);
    uint64_t b1lo = DESCB | ((uint64_t)((sb + SM_B1LO) >> 4) & 0x3FFF);

    // weight 0 -> buf0 -> D cols [0,128)
    tc_copyB(smem, SM_B0HI, SM_B0LO, w0, tid);
    asm volatile("fence.proxy.async.shared::cta;" ::: "memory");
    __syncthreads();
    if (wid == 0 && elect1())
        tc_issue_mma(tmem, ahi, alo, b0hi, b0lo, sb + SM_MB0);

    // weight 1 -> buf1 -> D cols [128,256)  (copy overlaps MMA0)
    if (w1 >= 0) {
        tc_copyB(smem, SM_B1HI, SM_B1LO, w1, tid);
        asm volatile("fence.proxy.async.shared::cta;" ::: "memory");
        __syncthreads();
        if (wid == 0 && elect1())
            tc_issue_mma(tmem + 128, ahi, alo, b1hi, b1lo, sb + SM_MB1);
    }

    // wait for MMA0 (frees buf0), then weight 2 -> buf0 -> D cols [256,384)
    mbar_wait(sb + SM_MB0, 0);
    asm volatile("tcgen05.fence::after_thread_sync;" ::: "memory");
    if (w2 >= 0) {
        tc_copyB(smem, SM_B0HI, SM_B0LO, w2, tid);
        asm volatile("fence.proxy.async.shared::cta;" ::: "memory");
        __syncthreads();
        if (wid == 0 && elect1())
            tc_issue_mma(tmem + 256, ahi, alo, b0hi, b0lo, sb + SM_MB2);
    }

    // epilogues (MMA1/MMA2 overlap these)
    tc_epilogue(tmem, M, row0, wid, lane, m0, b0, C0);
    if (w1 >= 0) {
        mbar_wait(sb + SM_MB1, 0);
        asm volatile("tcgen05.fence::after_thread_sync;" ::: "memory");
        tc_epilogue(tmem + 128, M, row0, wid, lane, m1, b1, C1);
    }
    if (w2 >= 0) {
        mbar_wait(sb + SM_MB2, 0);
        asm volatile("tcgen05.fence::after_thread_sync;" ::: "memory");
        tc_epilogue(tmem + 256, M, row0, wid, lane, m2, b2, C2);
    }
    asm volatile("tcgen05.fence::before_thread_sync;" ::: "memory");
    __syncthreads();

    if (tid == 0) {
        asm volatile("mbarrier.inval.shared.b64 [%0];" :: "r"(sb + SM_MB0) : "memory");
        asm volatile("mbarrier.inval.shared.b64 [%0];" :: "r"(sb + SM_MB1) : "memory");
        asm volatile("mbarrier.inval.shared.b64 [%0];" :: "r"(sb + SM_MB2) : "memory");
    }
    __syncthreads();
    if (wid == 0)
        asm volatile("tcgen05.dealloc.cta_group::1.sync.aligned.b32 %0, %1;"
                     :: "r"(tmem), "r"((uint32_t)TMEM_COLS));

#else  // ---------------- SIMT fp32 fallback (plain sm_103 pass) ----------------
    extern __shared__ float smf[];
    float* sA = smf;
    float* sW = smf + 16384;
    int tid = threadIdx.x;
    int row0 = blockIdx.x * 128;

    for (int i = tid; i < 4096; i += 256) {
        int r  = i >> 5;
        int gr = row0 + r;
        float4 v = make_float4(0.f, 0.f, 0.f, 0.f);
        if (gr < M) v = ((const float4*)A)[(size_t)gr * 32 + (i & 31)];
        ((float4*)sA)[i] = v;
    }

    const float* Wf[3] = {W0f, W1f, W2f};
    const float* bpf[3] = {b0, b1, b2};
    float* cpf[3] = {C0, C1, C2};
    int widxf[3] = {w0, w1, w2};
    int modef[3] = {m0, m1, m2};

    #pragma unroll 1
    for (int j = 0; j < 3; j++) {
        if (widxf[j] < 0) break;
        __syncthreads();
        for (int i = tid; i < 4096; i += 256)
            ((float4*)sW)[i] = ((const float4*)Wf[j])[i];
        __syncthreads();

        int rb = tid >> 4, cb = tid & 15;
        float acc[8][8];
        #pragma unroll
        for (int i = 0; i < 8; i++)
            #pragma unroll
            for (int q = 0; q < 8; q++) acc[i][q] = 0.f;

        #pragma unroll 4
        for (int k = 0; k < 128; k++) {
            float4 wv0 = *(const float4*)&sW[k * 128 + cb * 8];
            float4 wv1 = *(const float4*)&sW[k * 128 + cb * 8 + 4];
            float w[8] = {wv0.x, wv0.y, wv0.z, wv0.w, wv1.x, wv1.y, wv1.z, wv1.w};
            float a[8];
            #pragma unroll
            for (int i = 0; i < 8; i++) a[i] = sA[(rb * 8 + i) * 128 + k];
            #pragma unroll
            for (int i = 0; i < 8; i++)
                #pragma unroll
                for (int q = 0; q < 8; q++) acc[i][q] += a[i] * w[q];
        }

        #pragma unroll
        for (int i = 0; i < 8; i++) {
            int gr = row0 + rb * 8 + i;
            if (gr < M) {
                float* dst = cpf[j] + (size_t)gr * 128 + cb * 8;
                for (int q = 0; q < 8; q++) {
                    float o = acc[i][q];
                    if (modef[j] == 1)
                        o = g_mv[(size_t)gr * 128 + cb * 8 + q]
                          + g_t0[(size_t)(gr / 3) * 128 + cb * 8 + q] * o;
                    else if (bpf[j]) o += bpf[j][cb * 8 + q];
                    dst[q] = o;
                }
            }
        }
    }
#endif
}

// ---------------- P precompute ----------------
__global__ void pprep_kernel(const float* __restrict__ Wp1,
                             const float* __restrict__ Ws1)
{
    int idx = blockIdx.x * blockDim.x + threadIdx.x;
    if (idx >= GG * 512) return;
    int g  = idx >> 9;
    int hc = idx & 511;
    int h  = hc >> 6, c = hc & 63;
    const float* vp = g_val + (size_t)g * 128 + h * 16;
    float sp = 0.f, ss = 0.f;
    #pragma unroll
    for (int i = 0; i < 16; i++) {
        float v = vp[i];
        int wrow = (h * 16 + i) * 64 + c;
        sp += v * Wp1[wrow];
        ss += v * Ws1[wrow];
    }
    g_Pp[idx] = sp;
    g_Ps[idx] = ss;
}

// ---------------- fused edge kernel (unchanged — R3/R6 proven) ----------------
#define EO_WP2  0
#define EO_WS2  8192
#define EO_HP   16384
#define EO_HS   20480
#define EO_ATT  24576
#define EO_BP1  25088
#define EO_BS1  25152
#define EO_BP2  25216
#define EO_BS2  25344
#define EO_U    25472
#define EO_N    25664
#define EO_G    25728
#define EDGE_SMEM_FLOATS 25792

__global__ __launch_bounds__(256, 2) void edge_kernel(
    const int*   __restrict__ node_idx,
    const int*   __restrict__ group_idx,
    const float* __restrict__ edge_attr,
    const float* __restrict__ edge_vec,
    const float* __restrict__ bp1, const float* __restrict__ bs1,
    const float* __restrict__ Wp2, const float* __restrict__ bp2,
    const float* __restrict__ Ws2, const float* __restrict__ bs2,
    const float* __restrict__ gvec)
{
    extern __shared__ float sm[];
    float* sWp2  = sm + EO_WP2;
    float* sWs2  = sm + EO_WS2;
    float* s_hp  = sm + EO_HP;
    float* s_hs  = sm + EO_HS;
    float* s_attn= sm + EO_ATT;
    float* s_bp1 = sm + EO_BP1;
    float* s_bs1 = sm + EO_BS1;
    float* s_bp2 = sm + EO_BP2;
    float* s_bs2 = sm + EO_BS2;
    float* s_u   = sm + EO_U;
    int*   s_n   = (int*)(sm + EO_N);
    int*   s_g   = (int*)(sm + EO_G);

    int tid = threadIdx.x;

    for (int i = tid; i < 2048; i += 256) {
        ((float4*)sWp2)[i] = ((const float4*)Wp2)[i];
        ((float4*)sWs2)[i] = ((const float4*)Ws2)[i];
    }
    if (tid < 64)  { s_bp1[tid] = bp1[tid]; s_bs1[tid] = bs1[tid]; }
    if (tid < 128) { s_bp2[tid] = bp2[tid]; s_bs2[tid] = bs2[tid]; }
    __syncthreads();

    const int ntiles = EE / 64;
    for (int t = blockIdx.x; t < ntiles; t += gridDim.x) {
        int e0 = t * 64;

        if (tid < 64) {
            int e = e0 + tid;
            s_n[tid] = node_idx[e];
            s_g[tid] = group_idx[e];
            s_u[tid * 3 + 0] = -edge_vec[e * 3 + 0];
            s_u[tid * 3 + 1] = -edge_vec[e * 3 + 1];
            s_u[tid * 3 + 2] = -edge_vec[e * 3 + 2];
        }
        __syncthreads();

        #pragma unroll
        for (int p = tid; p < 512; p += 256) {
            int le = p >> 3, h = p & 7;
            const float4* qp = (const float4*)(g_q + (size_t)s_n[le] * 128 + h * 16);
            const float4* kp = (const float4*)(g_k + (size_t)s_g[le] * 128 + h * 16);
            const float4* ep = (const float4*)(edge_attr + (size_t)(e0 + le) * 128 + h * 16);
            float dot = 0.f;
            #pragma unroll
            for (int c = 0; c < 4; c++) {
                float4 qv = qp[c], kv = kp[c], ev = ep[c];
                dot += qv.x * kv.x * ev.x + qv.y * kv.y * ev.y
                     + qv.z * kv.z * ev.z + qv.w * kv.w * ev.w;
            }
            s_attn[le * 8 + h] = silu_f(dot * 0.25f);
        }
        __syncthreads();

        for (int i4 = tid; i4 < 2048; i4 += 256) {
            int le = i4 >> 5, j4 = i4 & 31;
            float4 v = ((const float4*)(g_val + (size_t)s_g[le] * 128))[j4];
            float  a = s_attn[le * 8 + (j4 >> 2)];
            float4 m = make_float4(v.x * a, v.y * a, v.z * a, v.w * a);
            atomicAdd((float4*)(g_ms + (size_t)s_n[le] * 128 + j4 * 4), m);
        }

        {
            int le = tid >> 2, cq = tid & 3, c0 = cq * 16;
            int g = s_g[le];
            float at[8];
            #pragma unroll
            for (int h = 0; h < 8; h++) at[h] = s_attn[le * 8 + h];
            float hp[16], hs[16];
            #pragma unroll
            for (int j = 0; j < 16; j++) { hp[j] = 0.f; hs[j] = 0.f; }
            const float4* Pp4 = (const float4*)(g_Pp + (size_t)g * 512);
            const float4* Ps4 = (const float4*)(g_Ps + (size_t)g * 512);
            #pragma unroll
            for (int h = 0; h < 8; h++) {
                int base = h * 16 + cq * 4;
                float ah = at[h];
                #pragma unroll
                for (int q = 0; q < 4; q++) {
                    float4 p = Pp4[base + q];
                    float4 s = Ps4[base + q];
                    hp[q*4+0] += ah * p.x; hp[q*4+1] += ah * p.y;
                    hp[q*4+2] += ah * p.z; hp[q*4+3] += ah * p.w;
                    hs[q*4+0] += ah * s.x; hs[q*4+1] += ah * s.y;
                    hs[q*4+2] += ah * s.z; hs[q*4+3] += ah * s.w;
                }
            }
            #pragma unroll
            for (int j = 0; j < 16; j++) {
                s_hp[le * 64 + c0 + j] = silu_f(hp[j] + s_bp1[c0 + j]);
                s_hs[le * 64 + c0 + j] = silu_f(hs[j] + s_bs1[c0 + j]);
            }
        }
        __syncthreads();

        {
            int rg = tid >> 4, cg = tid & 15;
            float sp[4][8], sv[4][8];
            #pragma unroll
            for (int i = 0; i < 4; i++)
                #pragma unroll
                for (int j = 0; j < 8; j++) { sp[i][j] = 0.f; sv[i][j] = 0.f; }

            #pragma unroll 2
            for (int k = 0; k < 64; k++) {
                float hp[4], hs[4];
                #pragma unroll
                for (int i = 0; i < 4; i++) {
                    hp[i] = s_hp[(rg * 4 + i) * 64 + k];
                    hs[i] = s_hs[(rg * 4 + i) * 64 + k];
                }
                float4 wpa = *(const float4*)&sWp2[k * 128 + cg * 8];
                float4 wpb = *(const float4*)&sWp2[k * 128 + cg * 8 + 4];
                float4 wsa = *(const float4*)&sWs2[k * 128 + cg * 8];
                float4 wsb = *(const float4*)&sWs2[k * 128 + cg * 8 + 4];
                float wp[8] = {wpa.x, wpa.y, wpa.z, wpa.w, wpb.x, wpb.y, wpb.z, wpb.w};
                float ws[8] = {wsa.x, wsa.y, wsa.z, wsa.w, wsb.x, wsb.y, wsb.z, wsb.w};
                #pragma unroll
                for (int i = 0; i < 4; i++)
                    #pragma unroll
                    for (int j = 0; j < 8; j++) {
                        sp[i][j] += hp[i] * wp[j];
                        sv[i][j] += hs[i] * ws[j];
                    }
            }

            float bp[8], bs[8];
            #pragma unroll
            for (int j = 0; j < 8; j++) { bp[j] = s_bp2[cg * 8 + j]; bs[j] = s_bs2[cg * 8 + j]; }

            #pragma unroll
            for (int i = 0; i < 4; i++) {
                int le = rg * 4 + i;
                int n = s_n[le], g = s_g[le];
                float spv[8], svv[8];
                #pragma unroll
                for (int j = 0; j < 8; j++) { spv[j] = sp[i][j] + bp[j]; svv[j] = sv[i][j] + bs[j]; }
                #pragma unroll
                for (int d = 0; d < 3; d++) {
                    float ud = s_u[le * 3 + d];
                    const float* gv = gvec + (size_t)g * 384 + d * 128 + cg * 8;
                    float4 g0 = *(const float4*)gv;
                    float4 g1 = *(const float4*)(gv + 4);
                    float4 o0 = make_float4(spv[0] * ud + svv[0] * g0.x,
                                            spv[1] * ud + svv[1] * g0.y,
                                            spv[2] * ud + svv[2] * g0.z,
                                            spv[3] * ud + svv[3] * g0.w);
                    float4 o1 = make_float4(spv[4] * ud + svv[4] * g1.x,
                                            spv[5] * ud + svv[5] * g1.y,
                                            spv[6] * ud + svv[6] * g1.z,
                                            spv[7] * ud + svv[7] * g1.w);
                    float* dst = g_mv + (size_t)n * 384 + d * 128 + cg * 8;
                    atomicAdd((float4*)dst, o0);
                    atomicAdd((float4*)(dst + 4), o1);
                }
            }
        }
        __syncthreads();
    }
}

// ---------------- finalize: dx only (dv fused into tc_gemm epilogue) ----------------
__global__ void finalize_kernel(float* __restrict__ out) {
    int idx = blockIdx.x * blockDim.x + threadIdx.x;
    if (idx >= NN * 32) return;
    int n = idx >> 5, j4 = idx & 31;
    size_t off = (size_t)n * 32 + j4;
    float4 t4 = ((const float4*)g_t4)[off];
    float4 t5 = ((const float4*)g_t5)[off];
    float4 s3 = make_float4(0.f, 0.f, 0.f, 0.f);
    #pragma unroll
    for (int d = 0; d < 3; d++) {
        size_t roff = ((size_t)n * 3 + d) * 32 + j4;
        float4 v1 = ((const float4*)g_v1)[roff];
        float4 v2 = ((const float4*)g_v2)[roff];
        s3.x += v1.x * v2.x; s3.y += v1.y * v2.y;
        s3.z += v1.z * v2.z; s3.w += v1.w * v2.w;
    }
    float4 dx = make_float4(s3.x * t4.x + t5.x, s3.y * t4.y + t5.y,
                            s3.z * t4.z + t5.z, s3.w * t4.w + t5.w);
    ((float4*)out)[off] = dx;
}

// ---------------- launch ----------------
extern "C" void kernel_launch(void* const* d_in, const int* in_sizes, int n_in,
                              void* d_out, int out_size)
{
    (void)in_sizes; (void)n_in; (void)out_size;
    const int*   node_idx   = (const int*)  d_in[0];
    const int*   group_idx  = (const int*)  d_in[1];
    const float* node_emb   = (const float*)d_in[2];
    const float* node_vec   = (const float*)d_in[3];
    const float* group_emb  = (const float*)d_in[4];
    const float* group_vec  = (const float*)d_in[5];
    const float* edge_attr  = (const float*)d_in[6];
    const float* edge_vec   = (const float*)d_in[8];
    const float* Wq  = (const float*)d_in[9];
    const float* bq  = (const float*)d_in[10];
    const float* Wk  = (const float*)d_in[11];
    const float* bk  = (const float*)d_in[12];
    const float* Wv  = (const float*)d_in[13];
    const float* bv  = (const float*)d_in[14];
    const float* Wp1 = (const float*)d_in[15];
    const float* bp1 = (const float*)d_in[16];
    const float* Wp2 = (const float*)d_in[17];
    const float* bp2 = (const float*)d_in[18];
    const float* Ws1 = (const float*)d_in[19];
    const float* bs1 = (const float*)d_in[20];
    const float* Ws2 = (const float*)d_in[21];
    const float* bs2 = (const float*)d_in[22];
    const float* L0  = (const float*)d_in[23];
    const float* L1  = (const float*)d_in[24];
    const float* L2  = (const float*)d_in[25];
    const float* L3  = (const float*)d_in[26];
    const float* L4  = (const float*)d_in[27];
    const float* L5  = (const float*)d_in[28];
    float* out = (float*)d_out;

    const size_t EDGE_SMEM = (size_t)EDGE_SMEM_FLOATS * sizeof(float);

    cudaFuncSetAttribute(tc_gemm, cudaFuncAttributeMaxDynamicSharedMemorySize, TC_SMEM);
    cudaFuncSetAttribute(edge_kernel, cudaFuncAttributeMaxDynamicSharedMemorySize,
                         (int)EDGE_SMEM);

    float *p_q, *p_k, *p_val, *p_ms, *p_mv, *p_t0, *p_t4, *p_t5, *p_v1, *p_v2;
    cudaGetSymbolAddress((void**)&p_q,  g_q);
    cudaGetSymbolAddress((void**)&p_k,  g_k);
    cudaGetSymbolAddress((void**)&p_val,g_val);
    cudaGetSymbolAddress((void**)&p_ms, g_ms);
    cudaGetSymbolAddress((void**)&p_mv, g_mv);
    cudaGetSymbolAddress((void**)&p_t0, g_t0);
    cudaGetSymbolAddress((void**)&p_t4, g_t4);
    cudaGetSymbolAddress((void**)&p_t5, g_t5);
    cudaGetSymbolAddress((void**)&p_v1, g_v1);
    cudaGetSymbolAddress((void**)&p_v2, g_v2);

    float* out_dv = out + (size_t)NN * 128;

    // 1) zero accumulators
    cudaMemsetAsync(p_ms, 0, (size_t)NN * 128 * sizeof(float));
    cudaMemsetAsync(p_mv, 0, (size_t)NN * 384 * sizeof(float));

    // 2) pre-convert all 9 dense weights (0=Wq 1=Wk 2=Wv 3=L0 4=L1 5=L2 6=L3 7=L4 8=L5)
    wconv_kernel<<<(9 * 8192 + 255) / 256, 256>>>(Wq, Wk, Wv, L0, L1, L2, L3, L4, L5);

    // 3) projections on tensor cores
    tc_gemm<<<(NN + 127) / 128, 256, TC_SMEM>>>(node_emb, NN,
        0, 0, Wq, bq, p_q,
        -1, 0, nullptr, nullptr, nullptr,
        -1, 0, nullptr, nullptr, nullptr);
    tc_gemm<<<(GG + 127) / 128, 256, TC_SMEM>>>(group_emb, GG,
        1, 0, Wk, bk, p_k,
        2, 0, Wv, bv, p_val,
        -1, 0, nullptr, nullptr, nullptr);

    // 4) per-group layer-1 factorization tables
    pprep_kernel<<<(GG * 512 + 255) / 256, 256>>>(Wp1, Ws1);

    // 5) fused edge pipeline
    edge_kernel<<<304, 256, EDGE_SMEM>>>(node_idx, group_idx, edge_attr, edge_vec,
                                         bp1, bs1, Wp2, bp2, Ws2, bs2, group_vec);

    // 6) node-side GEMMs: ms -> t0/t4/t5 ; node_vec -> dv (fused) / v1 / v2
    tc_gemm<<<(NN + 127) / 128, 256, TC_SMEM>>>(p_ms, NN,
        3, 0, L0, nullptr, p_t0,
        7, 0, L4, nullptr, p_t4,
        8, 0, L5, nullptr, p_t5);
    tc_gemm<<<(3 * NN + 127) / 128, 256, TC_SMEM>>>(node_vec, 3 * NN,
        4, 1, L1, nullptr, out_dv,
        5, 0, L2, nullptr, p_v1,
        6, 0, L3, nullptr, p_v2);

    // 7) finalize dx
    finalize_kernel<<<(NN * 32 + 255) / 256, 256>>>(out);
}

// round 8
// speedup vs baseline: 1.0722x; 1.0722x over previous
#include <cuda_runtime.h>
#include <cuda_bf16.h>
#include <math.h>
#include <stdint.h>

#define NN 100000
#define GG 6000
#define EE 400000

// ---------------- scratch (static __device__ — no allocs allowed) ----------------
__device__ float g_q  [NN * 128];
__device__ float g_k  [GG * 128];
__device__ float g_val[GG * 128];
__device__ float g_ms [NN * 128];
__device__ float g_mv [NN * 384];
__device__ float g_t0 [NN * 128];
__device__ float g_t4 [NN * 128];
__device__ float g_t5 [NN * 128];
__device__ float g_v1 [NN * 384];
__device__ float g_v2 [NN * 384];
__device__ float g_Pp [GG * 512];
__device__ float g_Ps [GG * 512];
__device__ uint32_t g_whi[9 * 8192];
__device__ uint32_t g_wlo[9 * 8192];
// group-sort scratch
__device__ int g_cnt [GG];
__device__ int g_cur [GG];
__device__ int g_perm[EE];

__device__ __forceinline__ float silu_f(float x) {
    return x / (1.0f + __expf(-x));
}

// blocked-atom SW128 byte offset for a [128 rows][128 cols bf16] tile
__device__ __forceinline__ uint32_t blk_off(int row, int col) {
    uint32_t off = (uint32_t)((row >> 3) + (col >> 6) * 16) * 1024u
                 + (uint32_t)(row & 7) * 128u + (uint32_t)(col & 63) * 2u;
    return off ^ ((off >> 3) & 0x70);
}

// ---------------- counting sort of edges by group ----------------
__global__ void hist_kernel(const int* __restrict__ gidx) {
    int e = blockIdx.x * 256 + threadIdx.x;
    if (e < EE) atomicAdd(&g_cnt[gidx[e]], 1);
}

__global__ void scan_kernel() {
    __shared__ int part[1024];
    int tid = threadIdx.x;
    int c0 = tid * 6;
    int local[6];
    int s = 0;
    #pragma unroll
    for (int i = 0; i < 6; i++) {
        int v = (c0 + i < GG) ? g_cnt[c0 + i] : 0;
        local[i] = s; s += v;
    }
    part[tid] = s;
    __syncthreads();
    for (int off = 1; off < 1024; off <<= 1) {
        int v = (tid >= off) ? part[tid - off] : 0;
        __syncthreads();
        part[tid] += v;
        __syncthreads();
    }
    int base = (tid > 0) ? part[tid - 1] : 0;
    #pragma unroll
    for (int i = 0; i < 6; i++)
        if (c0 + i < GG) g_cur[c0 + i] = base + local[i];
}

__global__ void scatter_kernel(const int* __restrict__ gidx) {
    int e = blockIdx.x * 256 + threadIdx.x;
    if (e < EE) {
        int pos = atomicAdd(&g_cur[gidx[e]], 1);
        g_perm[pos] = e;
    }
}

// ---------------- weight conversion: W[k][n] fp32 -> B[n][k] bf16 hi/lo ----------------
__global__ void wconv_kernel(
    const float* __restrict__ W0, const float* __restrict__ W1,
    const float* __restrict__ W2, const float* __restrict__ W3,
    const float* __restrict__ W4, const float* __restrict__ W5,
    const float* __restrict__ W6, const float* __restrict__ W7,
    const float* __restrict__ W8)
{
    const float* Ws[9] = {W0, W1, W2, W3, W4, W5, W6, W7, W8};
    int gidx = blockIdx.x * 256 + threadIdx.x;
    if (gidx >= 9 * 8192) return;
    int w = gidx >> 13, p = gidx & 8191;
    int n = p >> 6, k2 = (p & 63) * 2;
    const float* W = Ws[w];
    float x0 = W[k2 * 128 + n], x1 = W[(k2 + 1) * 128 + n];
    __nv_bfloat16 h0 = __float2bfloat16(x0), h1 = __float2bfloat16(x1);
    float r0 = x0 - __bfloat162float(h0), r1 = x1 - __bfloat162float(h1);
    __nv_bfloat16 l0 = __float2bfloat16(r0), l1 = __float2bfloat16(r1);
    uint32_t o = blk_off(n, k2) >> 2;
    g_whi[w * 8192 + o] = (uint32_t)__bfloat16_as_ushort(h0)
                        | ((uint32_t)__bfloat16_as_ushort(h1) << 16);
    g_wlo[w * 8192 + o] = (uint32_t)__bfloat16_as_ushort(l0)
                        | ((uint32_t)__bfloat16_as_ushort(l1) << 16);
}

// ---------------- arch-specific PTX helpers (guarded) ----------------
#if defined(__CUDA_ARCH_FEAT_SM103_ALL) || !defined(__CUDA_ARCH__)
#define HAVE_TCGEN05 1
#else
#define HAVE_TCGEN05 0
#endif

__device__ __forceinline__ uint32_t smem_u32(const void* p) {
    uint32_t a;
    asm("{ .reg .u64 t; cvta.to.shared.u64 t, %1; cvt.u32.u64 %0, t; }"
        : "=r"(a) : "l"(p));
    return a;
}

#if HAVE_TCGEN05
__device__ __forceinline__ uint32_t elect1() {
    uint32_t p;
    asm volatile("{\n\t.reg .pred p;\n\telect.sync _|p, 0xFFFFFFFF;\n\t"
                 "selp.b32 %0, 1, 0, p;\n\t}" : "=r"(p));
    return p;
}
__device__ __forceinline__ void mma_f16_ss(uint32_t d, uint64_t a, uint64_t b,
                                           uint32_t idesc, uint32_t en) {
    asm volatile("{\n\t.reg .pred p;\n\tsetp.ne.u32 p, %5, 0;\n\t"
                 "tcgen05.mma.cta_group::1.kind::f16 [%0], %1, %2, %3, {%4,%4,%4,%4}, p;\n\t}"
                 :: "r"(d), "l"(a), "l"(b), "r"(idesc), "r"(0u), "r"(en) : "memory");
}
__device__ __forceinline__ void mbar_wait(uint32_t mbar, uint32_t parity) {
    uint32_t done;
    asm volatile("{\n\t.reg .pred p;\n\t"
                 "mbarrier.try_wait.parity.acquire.cta.shared::cta.b64 p, [%1], %2;\n\t"
                 "selp.b32 %0, 1, 0, p;\n\t}"
                 : "=r"(done) : "r"(mbar), "r"(parity) : "memory");
    if (!done) {
        asm volatile("{\n\t.reg .pred P1;\n\t"
                     "WAIT_LOOP_%=:\n\t"
                     "mbarrier.try_wait.parity.acquire.cta.shared::cta.b64 P1, [%0], %1, 0x989680;\n\t"
                     "@P1 bra.uni WAIT_DONE_%=;\n\t"
                     "bra.uni WAIT_LOOP_%=;\n\t"
                     "WAIT_DONE_%=:\n\t}"
                     :: "r"(mbar), "r"(parity) : "memory");
    }
}
#define LDTM_X32(r, addr) \
    asm volatile( \
        "tcgen05.ld.sync.aligned.32x32b.x32.b32 " \
        "{%0, %1, %2, %3, %4, %5, %6, %7, " \
        " %8, %9, %10, %11, %12, %13, %14, %15, " \
        " %16, %17, %18, %19, %20, %21, %22, %23, " \
        " %24, %25, %26, %27, %28, %29, %30, %31}, [%32];" \
        : "=r"((r)[0]),  "=r"((r)[1]),  "=r"((r)[2]),  "=r"((r)[3]), \
          "=r"((r)[4]),  "=r"((r)[5]),  "=r"((r)[6]),  "=r"((r)[7]), \
          "=r"((r)[8]),  "=r"((r)[9]),  "=r"((r)[10]), "=r"((r)[11]), \
          "=r"((r)[12]), "=r"((r)[13]), "=r"((r)[14]), "=r"((r)[15]), \
          "=r"((r)[16]), "=r"((r)[17]), "=r"((r)[18]), "=r"((r)[19]), \
          "=r"((r)[20]), "=r"((r)[21]), "=r"((r)[22]), "=r"((r)[23]), \
          "=r"((r)[24]), "=r"((r)[25]), "=r"((r)[26]), "=r"((r)[27]), \
          "=r"((r)[28]), "=r"((r)[29]), "=r"((r)[30]), "=r"((r)[31]) \
        : "r"(addr))
#endif  // HAVE_TCGEN05

// ---------------- pipelined tcgen05 GEMM: up to 3 weights, TMEM ping-pong ----------------
// mode 0: C = A@W (+bias). mode 1: C = g_mv + g_t0[row/3] * (A@W)   (dv fusion)
#define SM_TMEM 0
#define SM_MB0  8
#define SM_MB1  16
#define SM_MB2  24
#define SM_AHI  1024
#define SM_ALO  33792
#define SM_B0HI 66560
#define SM_B0LO 99328
#define SM_B1HI 132096
#define SM_B1LO 164864
#define TC_SMEM 197632
#define TMEM_COLS 512

#if HAVE_TCGEN05
__device__ __forceinline__ void tc_copyB(char* smem, uint32_t dsthi, uint32_t dstlo,
                                         int w, int tid)
{
    const uint4* shi = (const uint4*)(g_whi + w * 8192);
    const uint4* slo = (const uint4*)(g_wlo + w * 8192);
    uint4* dhi = (uint4*)(smem + dsthi);
    uint4* dlo = (uint4*)(smem + dstlo);
    for (int i = tid; i < 2048; i += 256) { dhi[i] = shi[i]; dlo[i] = slo[i]; }
}

__device__ __forceinline__ void tc_issue_mma(uint32_t tmem_d, uint64_t ahi, uint64_t alo,
                                             uint64_t bhi, uint64_t blo, uint32_t mbar)
{
    const uint32_t IDESC = (1u << 4) | (1u << 7) | (1u << 10) | (16u << 17) | (8u << 24);
    uint32_t en = 0;
    #pragma unroll
    for (int kc = 0; kc < 8; kc++) {
        uint64_t ko = (uint64_t)((kc & 3) * 2 + (kc >> 2) * 1024);
        mma_f16_ss(tmem_d, ahi + ko, bhi + ko, IDESC, en); en = 1;
    }
    #pragma unroll
    for (int kc = 0; kc < 8; kc++) {
        uint64_t ko = (uint64_t)((kc & 3) * 2 + (kc >> 2) * 1024);
        mma_f16_ss(tmem_d, ahi + ko, blo + ko, IDESC, 1);
    }
    #pragma unroll
    for (int kc = 0; kc < 8; kc++) {
        uint64_t ko = (uint64_t)((kc & 3) * 2 + (kc >> 2) * 1024);
        mma_f16_ss(tmem_d, alo + ko, bhi + ko, IDESC, 1);
    }
    asm volatile("tcgen05.commit.cta_group::1.mbarrier::arrive::one.shared::cluster.b64 [%0];"
                 :: "r"(mbar) : "memory");
}

__device__ __forceinline__ void tc_epilogue(uint32_t tmem_d, int M, int row0,
                                            int wid, int lane, int mode,
                                            const float* bias, float* C)
{
    if (wid >= 4) return;
    int gr = row0 + wid * 32 + lane;
    #pragma unroll 1
    for (int cb = 0; cb < 4; cb++) {
        uint32_t d[32];
        LDTM_X32(d, tmem_d + cb * 32);
        asm volatile("tcgen05.wait::ld.sync.aligned;" ::: "memory");
        if (gr < M) {
            float* dst = C + (size_t)gr * 128 + cb * 32;
            if (mode == 1) {
                const float4* mvp = (const float4*)(g_mv + (size_t)gr * 128 + cb * 32);
                const float4* t0p = (const float4*)(g_t0 + (size_t)(gr / 3) * 128 + cb * 32);
                #pragma unroll
                for (int q = 0; q < 8; q++) {
                    float4 mv = mvp[q], t0 = t0p[q];
                    float4 o;
                    o.x = mv.x + t0.x * __uint_as_float(d[q * 4 + 0]);
                    o.y = mv.y + t0.y * __uint_as_float(d[q * 4 + 1]);
                    o.z = mv.z + t0.z * __uint_as_float(d[q * 4 + 2]);
                    o.w = mv.w + t0.w * __uint_as_float(d[q * 4 + 3]);
                    ((float4*)dst)[q] = o;
                }
            } else {
                #pragma unroll
                for (int q = 0; q < 8; q++) {
                    float4 o;
                    o.x = __uint_as_float(d[q * 4 + 0]);
                    o.y = __uint_as_float(d[q * 4 + 1]);
                    o.z = __uint_as_float(d[q * 4 + 2]);
                    o.w = __uint_as_float(d[q * 4 + 3]);
                    if (bias) {
                        const float* bb = bias + cb * 32 + q * 4;
                        o.x += bb[0]; o.y += bb[1]; o.z += bb[2]; o.w += bb[3];
                    }
                    ((float4*)dst)[q] = o;
                }
            }
        }
    }
}
#endif  // HAVE_TCGEN05

__global__ __launch_bounds__(256, 1) __cluster_dims__(1, 1, 1)
void tc_gemm(const float* __restrict__ A, int M,
             int w0, int m0, const float* __restrict__ W0f, const float* __restrict__ b0, float* __restrict__ C0,
             int w1, int m1, const float* __restrict__ W1f, const float* __restrict__ b1, float* __restrict__ C1,
             int w2, int m2, const float* __restrict__ W2f, const float* __restrict__ b2, float* __restrict__ C2)
{
#if HAVE_TCGEN05
    extern __shared__ char smem[];
    uint32_t sb = smem_u32(smem);
    int tid = threadIdx.x, wid = tid >> 5, lane = tid & 31;
    int row0 = blockIdx.x * 128;

    if (wid == 0)
        asm volatile("tcgen05.alloc.cta_group::1.sync.aligned.shared::cta.b32 [%0], %1;"
                     :: "r"(sb + SM_TMEM), "r"((uint32_t)TMEM_COLS) : "memory");
    if (tid == 0) {
        asm volatile("mbarrier.init.shared.b64 [%0], 1;" :: "r"(sb + SM_MB0) : "memory");
        asm volatile("mbarrier.init.shared.b64 [%0], 1;" :: "r"(sb + SM_MB1) : "memory");
        asm volatile("mbarrier.init.shared.b64 [%0], 1;" :: "r"(sb + SM_MB2) : "memory");
    }
    __syncthreads();
    uint32_t tmem;
    asm volatile("ld.shared.b32 %0, [%1];" : "=r"(tmem) : "r"(sb + SM_TMEM));

    for (int p = tid; p < 8192; p += 256) {
        int r = p >> 6, k2 = (p & 63) * 2;
        float2 x = make_float2(0.f, 0.f);
        if (row0 + r < M) x = *(const float2*)(A + (size_t)(row0 + r) * 128 + k2);
        __nv_bfloat16 h0 = __float2bfloat16(x.x), h1 = __float2bfloat16(x.y);
        float r0f = x.x - __bfloat162float(h0), r1f = x.y - __bfloat162float(h1);
        __nv_bfloat16 l0 = __float2bfloat16(r0f), l1 = __float2bfloat16(r1f);
        uint32_t hiw = (uint32_t)__bfloat16_as_ushort(h0)
                     | ((uint32_t)__bfloat16_as_ushort(h1) << 16);
        uint32_t low = (uint32_t)__bfloat16_as_ushort(l0)
                     | ((uint32_t)__bfloat16_as_ushort(l1) << 16);
        uint32_t off = blk_off(r, k2);
        *(uint32_t*)(smem + SM_AHI + off) = hiw;
        *(uint32_t*)(smem + SM_ALO + off) = low;
    }

    const uint64_t DESCB = (2ull << 61) | (1ull << 46) | (64ull << 32) | (1ull << 16);
    uint64_t ahi  = DESCB | ((uint64_t)((sb + SM_AHI)  >> 4) & 0x3FFF);
    uint64_t alo  = DESCB | ((uint64_t)((sb + SM_ALO)  >> 4) & 0x3FFF);
    uint64_t b0hi = DESCB | ((uint64_t)((sb + SM_B0HI) >> 4) & 0x3FFF);
    uint64_t b0lo = DESCB | ((uint64_t)((sb + SM_B0LO) >> 4) & 0x3FFF);
    uint64_t b1hi = DESCB | ((uint64_t)((sb + SM_B1HI) >> 4) & 0x3FFF);
    uint64_t b1lo = DESCB | ((uint64_t)((sb + SM_B1LO) >> 4) & 0x3FFF);

    tc_copyB(smem, SM_B0HI, SM_B0LO, w0, tid);
    asm volatile("fence.proxy.async.shared::cta;" ::: "memory");
    __syncthreads();
    if (wid == 0 && elect1())
        tc_issue_mma(tmem, ahi, alo, b0hi, b0lo, sb + SM_MB0);

    if (w1 >= 0) {
        tc_copyB(smem, SM_B1HI, SM_B1LO, w1, tid);
        asm volatile("fence.proxy.async.shared::cta;" ::: "memory");
        __syncthreads();
        if (wid == 0 && elect1())
            tc_issue_mma(tmem + 128, ahi, alo, b1hi, b1lo, sb + SM_MB1);
    }

    mbar_wait(sb + SM_MB0, 0);
    asm volatile("tcgen05.fence::after_thread_sync;" ::: "memory");
    if (w2 >= 0) {
        tc_copyB(smem, SM_B0HI, SM_B0LO, w2, tid);
        asm volatile("fence.proxy.async.shared::cta;" ::: "memory");
        __syncthreads();
        if (wid == 0 && elect1())
            tc_issue_mma(tmem + 256, ahi, alo, b0hi, b0lo, sb + SM_MB2);
    }

    tc_epilogue(tmem, M, row0, wid, lane, m0, b0, C0);
    if (w1 >= 0) {
        mbar_wait(sb + SM_MB1, 0);
        asm volatile("tcgen05.fence::after_thread_sync;" ::: "memory");
        tc_epilogue(tmem + 128, M, row0, wid, lane, m1, b1, C1);
    }
    if (w2 >= 0) {
        mbar_wait(sb + SM_MB2, 0);
        asm volatile("tcgen05.fence::after_thread_sync;" ::: "memory");
        tc_epilogue(tmem + 256, M, row0, wid, lane, m2, b2, C2);
    }
    asm volatile("tcgen05.fence::before_thread_sync;" ::: "memory");
    __syncthreads();

    if (tid == 0) {
        asm volatile("mbarrier.inval.shared.b64 [%0];" :: "r"(sb + SM_MB0) : "memory");
        asm volatile("mbarrier.inval.shared.b64 [%0];" :: "r"(sb + SM_MB1) : "memory");
        asm volatile("mbarrier.inval.shared.b64 [%0];" :: "r"(sb + SM_MB2) : "memory");
    }
    __syncthreads();
    if (wid == 0)
        asm volatile("tcgen05.dealloc.cta_group::1.sync.aligned.b32 %0, %1;"
                     :: "r"(tmem), "r"((uint32_t)TMEM_COLS));

#else  // ---------------- SIMT fp32 fallback (plain sm_103 pass) ----------------
    extern __shared__ float smf[];
    float* sA = smf;
    float* sW = smf + 16384;
    int tid = threadIdx.x;
    int row0 = blockIdx.x * 128;

    for (int i = tid; i < 4096; i += 256) {
        int r  = i >> 5;
        int gr = row0 + r;
        float4 v = make_float4(0.f, 0.f, 0.f, 0.f);
        if (gr < M) v = ((const float4*)A)[(size_t)gr * 32 + (i & 31)];
        ((float4*)sA)[i] = v;
    }

    const float* Wf[3] = {W0f, W1f, W2f};
    const float* bpf[3] = {b0, b1, b2};
    float* cpf[3] = {C0, C1, C2};
    int widxf[3] = {w0, w1, w2};
    int modef[3] = {m0, m1, m2};

    #pragma unroll 1
    for (int j = 0; j < 3; j++) {
        if (widxf[j] < 0) break;
        __syncthreads();
        for (int i = tid; i < 4096; i += 256)
            ((float4*)sW)[i] = ((const float4*)Wf[j])[i];
        __syncthreads();

        int rb = tid >> 4, cb = tid & 15;
        float acc[8][8];
        #pragma unroll
        for (int i = 0; i < 8; i++)
            #pragma unroll
            for (int q = 0; q < 8; q++) acc[i][q] = 0.f;

        #pragma unroll 4
        for (int k = 0; k < 128; k++) {
            float4 wv0 = *(const float4*)&sW[k * 128 + cb * 8];
            float4 wv1 = *(const float4*)&sW[k * 128 + cb * 8 + 4];
            float w[8] = {wv0.x, wv0.y, wv0.z, wv0.w, wv1.x, wv1.y, wv1.z, wv1.w};
            float a[8];
            #pragma unroll
            for (int i = 0; i < 8; i++) a[i] = sA[(rb * 8 + i) * 128 + k];
            #pragma unroll
            for (int i = 0; i < 8; i++)
                #pragma unroll
                for (int q = 0; q < 8; q++) acc[i][q] += a[i] * w[q];
        }

        #pragma unroll
        for (int i = 0; i < 8; i++) {
            int gr = row0 + rb * 8 + i;
            if (gr < M) {
                float* dst = cpf[j] + (size_t)gr * 128 + cb * 8;
                for (int q = 0; q < 8; q++) {
                    float o = acc[i][q];
                    if (modef[j] == 1)
                        o = g_mv[(size_t)gr * 128 + cb * 8 + q]
                          + g_t0[(size_t)(gr / 3) * 128 + cb * 8 + q] * o;
                    else if (bpf[j]) o += bpf[j][cb * 8 + q];
                    dst[q] = o;
                }
            }
        }
    }
#endif
}

// ---------------- P precompute ----------------
__global__ void pprep_kernel(const float* __restrict__ Wp1,
                             const float* __restrict__ Ws1)
{
    int idx = blockIdx.x * blockDim.x + threadIdx.x;
    if (idx >= GG * 512) return;
    int g  = idx >> 9;
    int hc = idx & 511;
    int h  = hc >> 6, c = hc & 63;
    const float* vp = g_val + (size_t)g * 128 + h * 16;
    float sp = 0.f, ss = 0.f;
    #pragma unroll
    for (int i = 0; i < 16; i++) {
        float v = vp[i];
        int wrow = (h * 16 + i) * 64 + c;
        sp += v * Wp1[wrow];
        ss += v * Ws1[wrow];
    }
    g_Pp[idx] = sp;
    g_Ps[idx] = ss;
}

// ---------------- fused edge kernel (group-sorted via g_perm) ----------------
#define EO_WP2  0
#define EO_WS2  8192
#define EO_HP   16384
#define EO_HS   20480
#define EO_ATT  24576
#define EO_BP1  25088
#define EO_BS1  25152
#define EO_BP2  25216
#define EO_BS2  25344
#define EO_U    25472
#define EO_N    25664
#define EO_G    25728
#define EO_E    25792
#define EDGE_SMEM_FLOATS 25856

__global__ __launch_bounds__(256, 2) void edge_kernel(
    const int*   __restrict__ node_idx,
    const int*   __restrict__ group_idx,
    const float* __restrict__ edge_attr,
    const float* __restrict__ edge_vec,
    const float* __restrict__ bp1, const float* __restrict__ bs1,
    const float* __restrict__ Wp2, const float* __restrict__ bp2,
    const float* __restrict__ Ws2, const float* __restrict__ bs2,
    const float* __restrict__ gvec)
{
    extern __shared__ float sm[];
    float* sWp2  = sm + EO_WP2;
    float* sWs2  = sm + EO_WS2;
    float* s_hp  = sm + EO_HP;
    float* s_hs  = sm + EO_HS;
    float* s_attn= sm + EO_ATT;
    float* s_bp1 = sm + EO_BP1;
    float* s_bs1 = sm + EO_BS1;
    float* s_bp2 = sm + EO_BP2;
    float* s_bs2 = sm + EO_BS2;
    float* s_u   = sm + EO_U;
    int*   s_n   = (int*)(sm + EO_N);
    int*   s_g   = (int*)(sm + EO_G);
    int*   s_e   = (int*)(sm + EO_E);

    int tid = threadIdx.x;

    for (int i = tid; i < 2048; i += 256) {
        ((float4*)sWp2)[i] = ((const float4*)Wp2)[i];
        ((float4*)sWs2)[i] = ((const float4*)Ws2)[i];
    }
    if (tid < 64)  { s_bp1[tid] = bp1[tid]; s_bs1[tid] = bs1[tid]; }
    if (tid < 128) { s_bp2[tid] = bp2[tid]; s_bs2[tid] = bs2[tid]; }
    __syncthreads();

    const int ntiles = EE / 64;
    for (int t = blockIdx.x; t < ntiles; t += gridDim.x) {
        int e0 = t * 64;

        if (tid < 64) {
            int e = g_perm[e0 + tid];          // group-sorted order
            s_e[tid] = e;
            s_n[tid] = node_idx[e];
            s_g[tid] = group_idx[e];
            s_u[tid * 3 + 0] = -edge_vec[e * 3 + 0];
            s_u[tid * 3 + 1] = -edge_vec[e * 3 + 1];
            s_u[tid * 3 + 2] = -edge_vec[e * 3 + 2];
        }
        __syncthreads();

        #pragma unroll
        for (int p = tid; p < 512; p += 256) {
            int le = p >> 3, h = p & 7;
            const float4* qp = (const float4*)(g_q + (size_t)s_n[le] * 128 + h * 16);
            const float4* kp = (const float4*)(g_k + (size_t)s_g[le] * 128 + h * 16);
            const float4* ep = (const float4*)(edge_attr + (size_t)s_e[le] * 128 + h * 16);
            float dot = 0.f;
            #pragma unroll
            for (int c = 0; c < 4; c++) {
                float4 qv = qp[c], kv = kp[c], ev = ep[c];
                dot += qv.x * kv.x * ev.x + qv.y * kv.y * ev.y
                     + qv.z * kv.z * ev.z + qv.w * kv.w * ev.w;
            }
            s_attn[le * 8 + h] = silu_f(dot * 0.25f);
        }
        __syncthreads();

        for (int i4 = tid; i4 < 2048; i4 += 256) {
            int le = i4 >> 5, j4 = i4 & 31;
            float4 v = ((const float4*)(g_val + (size_t)s_g[le] * 128))[j4];
            float  a = s_attn[le * 8 + (j4 >> 2)];
            float4 m = make_float4(v.x * a, v.y * a, v.z * a, v.w * a);
            atomicAdd((float4*)(g_ms + (size_t)s_n[le] * 128 + j4 * 4), m);
        }

        {
            int le = tid >> 2, cq = tid & 3, c0 = cq * 16;
            int g = s_g[le];
            float at[8];
            #pragma unroll
            for (int h = 0; h < 8; h++) at[h] = s_attn[le * 8 + h];
            float hp[16], hs[16];
            #pragma unroll
            for (int j = 0; j < 16; j++) { hp[j] = 0.f; hs[j] = 0.f; }
            const float4* Pp4 = (const float4*)(g_Pp + (size_t)g * 512);
            const float4* Ps4 = (const float4*)(g_Ps + (size_t)g * 512);
            #pragma unroll
            for (int h = 0; h < 8; h++) {
                int base = h * 16 + cq * 4;
                float ah = at[h];
                #pragma unroll
                for (int q = 0; q < 4; q++) {
                    float4 p = Pp4[base + q];
                    float4 s = Ps4[base + q];
                    hp[q*4+0] += ah * p.x; hp[q*4+1] += ah * p.y;
                    hp[q*4+2] += ah * p.z; hp[q*4+3] += ah * p.w;
                    hs[q*4+0] += ah * s.x; hs[q*4+1] += ah * s.y;
                    hs[q*4+2] += ah * s.z; hs[q*4+3] += ah * s.w;
                }
            }
            #pragma unroll
            for (int j = 0; j < 16; j++) {
                s_hp[le * 64 + c0 + j] = silu_f(hp[j] + s_bp1[c0 + j]);
                s_hs[le * 64 + c0 + j] = silu_f(hs[j] + s_bs1[c0 + j]);
            }
        }
        __syncthreads();

        {
            int rg = tid >> 4, cg = tid & 15;
            float sp[4][8], sv[4][8];
            #pragma unroll
            for (int i = 0; i < 4; i++)
                #pragma unroll
                for (int j = 0; j < 8; j++) { sp[i][j] = 0.f; sv[i][j] = 0.f; }

            #pragma unroll 2
            for (int k = 0; k < 64; k++) {
                float hp[4], hs[4];
                #pragma unroll
                for (int i = 0; i < 4; i++) {
                    hp[i] = s_hp[(rg * 4 + i) * 64 + k];
                    hs[i] = s_hs[(rg * 4 + i) * 64 + k];
                }
                float4 wpa = *(const float4*)&sWp2[k * 128 + cg * 8];
                float4 wpb = *(const float4*)&sWp2[k * 128 + cg * 8 + 4];
                float4 wsa = *(const float4*)&sWs2[k * 128 + cg * 8];
                float4 wsb = *(const float4*)&sWs2[k * 128 + cg * 8 + 4];
                float wp[8] = {wpa.x, wpa.y, wpa.z, wpa.w, wpb.x, wpb.y, wpb.z, wpb.w};
                float ws[8] = {wsa.x, wsa.y, wsa.z, wsa.w, wsb.x, wsb.y, wsb.z, wsb.w};
                #pragma unroll
                for (int i = 0; i < 4; i++)
                    #pragma unroll
                    for (int j = 0; j < 8; j++) {
                        sp[i][j] += hp[i] * wp[j];
                        sv[i][j] += hs[i] * ws[j];
                    }
            }

            float bp[8], bs[8];
            #pragma unroll
            for (int j = 0; j < 8; j++) { bp[j] = s_bp2[cg * 8 + j]; bs[j] = s_bs2[cg * 8 + j]; }

            #pragma unroll
            for (int i = 0; i < 4; i++) {
                int le = rg * 4 + i;
                int n = s_n[le], g = s_g[le];
                float spv[8], svv[8];
                #pragma unroll
                for (int j = 0; j < 8; j++) { spv[j] = sp[i][j] + bp[j]; svv[j] = sv[i][j] + bs[j]; }
                #pragma unroll
                for (int d = 0; d < 3; d++) {
                    float ud = s_u[le * 3 + d];
                    const float* gv = gvec + (size_t)g * 384 + d * 128 + cg * 8;
                    float4 g0 = *(const float4*)gv;
                    float4 g1 = *(const float4*)(gv + 4);
                    float4 o0 = make_float4(spv[0] * ud + svv[0] * g0.x,
                                            spv[1] * ud + svv[1] * g0.y,
                                            spv[2] * ud + svv[2] * g0.z,
                                            spv[3] * ud + svv[3] * g0.w);
                    float4 o1 = make_float4(spv[4] * ud + svv[4] * g1.x,
                                            spv[5] * ud + svv[5] * g1.y,
                                            spv[6] * ud + svv[6] * g1.z,
                                            spv[7] * ud + svv[7] * g1.w);
                    float* dst = g_mv + (size_t)n * 384 + d * 128 + cg * 8;
                    atomicAdd((float4*)dst, o0);
                    atomicAdd((float4*)(dst + 4), o1);
                }
            }
        }
        __syncthreads();
    }
}

// ---------------- finalize: dx only (dv fused into tc_gemm epilogue) ----------------
__global__ void finalize_kernel(float* __restrict__ out) {
    int idx = blockIdx.x * blockDim.x + threadIdx.x;
    if (idx >= NN * 32) return;
    int n = idx >> 5, j4 = idx & 31;
    size_t off = (size_t)n * 32 + j4;
    float4 t4 = ((const float4*)g_t4)[off];
    float4 t5 = ((const float4*)g_t5)[off];
    float4 s3 = make_float4(0.f, 0.f, 0.f, 0.f);
    #pragma unroll
    for (int d = 0; d < 3; d++) {
        size_t roff = ((size_t)n * 3 + d) * 32 + j4;
        float4 v1 = ((const float4*)g_v1)[roff];
        float4 v2 = ((const float4*)g_v2)[roff];
        s3.x += v1.x * v2.x; s3.y += v1.y * v2.y;
        s3.z += v1.z * v2.z; s3.w += v1.w * v2.w;
    }
    float4 dx = make_float4(s3.x * t4.x + t5.x, s3.y * t4.y + t5.y,
                            s3.z * t4.z + t5.z, s3.w * t4.w + t5.w);
    ((float4*)out)[off] = dx;
}

// ---------------- launch ----------------
extern "C" void kernel_launch(void* const* d_in, const int* in_sizes, int n_in,
                              void* d_out, int out_size)
{
    (void)in_sizes; (void)n_in; (void)out_size;
    const int*   node_idx   = (const int*)  d_in[0];
    const int*   group_idx  = (const int*)  d_in[1];
    const float* node_emb   = (const float*)d_in[2];
    const float* node_vec   = (const float*)d_in[3];
    const float* group_emb  = (const float*)d_in[4];
    const float* group_vec  = (const float*)d_in[5];
    const float* edge_attr  = (const float*)d_in[6];
    const float* edge_vec   = (const float*)d_in[8];
    const float* Wq  = (const float*)d_in[9];
    const float* bq  = (const float*)d_in[10];
    const float* Wk  = (const float*)d_in[11];
    const float* bk  = (const float*)d_in[12];
    const float* Wv  = (const float*)d_in[13];
    const float* bv  = (const float*)d_in[14];
    const float* Wp1 = (const float*)d_in[15];
    const float* bp1 = (const float*)d_in[16];
    const float* Wp2 = (const float*)d_in[17];
    const float* bp2 = (const float*)d_in[18];
    const float* Ws1 = (const float*)d_in[19];
    const float* bs1 = (const float*)d_in[20];
    const float* Ws2 = (const float*)d_in[21];
    const float* bs2 = (const float*)d_in[22];
    const float* L0  = (const float*)d_in[23];
    const float* L1  = (const float*)d_in[24];
    const float* L2  = (const float*)d_in[25];
    const float* L3  = (const float*)d_in[26];
    const float* L4  = (const float*)d_in[27];
    const float* L5  = (const float*)d_in[28];
    float* out = (float*)d_out;

    const size_t EDGE_SMEM = (size_t)EDGE_SMEM_FLOATS * sizeof(float);

    cudaFuncSetAttribute(tc_gemm, cudaFuncAttributeMaxDynamicSharedMemorySize, TC_SMEM);
    cudaFuncSetAttribute(edge_kernel, cudaFuncAttributeMaxDynamicSharedMemorySize,
                         (int)EDGE_SMEM);

    float *p_q, *p_k, *p_val, *p_ms, *p_mv, *p_t0, *p_t4, *p_t5, *p_v1, *p_v2;
    int *p_cnt;
    cudaGetSymbolAddress((void**)&p_q,  g_q);
    cudaGetSymbolAddress((void**)&p_k,  g_k);
    cudaGetSymbolAddress((void**)&p_val,g_val);
    cudaGetSymbolAddress((void**)&p_ms, g_ms);
    cudaGetSymbolAddress((void**)&p_mv, g_mv);
    cudaGetSymbolAddress((void**)&p_t0, g_t0);
    cudaGetSymbolAddress((void**)&p_t4, g_t4);
    cudaGetSymbolAddress((void**)&p_t5, g_t5);
    cudaGetSymbolAddress((void**)&p_v1, g_v1);
    cudaGetSymbolAddress((void**)&p_v2, g_v2);
    cudaGetSymbolAddress((void**)&p_cnt, g_cnt);

    float* out_dv = out + (size_t)NN * 128;

    // 1) zero accumulators + sort scratch
    cudaMemsetAsync(p_ms, 0, (size_t)NN * 128 * sizeof(float));
    cudaMemsetAsync(p_mv, 0, (size_t)NN * 384 * sizeof(float));
    cudaMemsetAsync(p_cnt, 0, (size_t)GG * sizeof(int));

    // 2) group-sort the edges (counting sort)
    hist_kernel<<<(EE + 255) / 256, 256>>>(group_idx);
    scan_kernel<<<1, 1024>>>();
    scatter_kernel<<<(EE + 255) / 256, 256>>>(group_idx);

    // 3) pre-convert all 9 dense weights (0=Wq 1=Wk 2=Wv 3=L0 4=L1 5=L2 6=L3 7=L4 8=L5)
    wconv_kernel<<<(9 * 8192 + 255) / 256, 256>>>(Wq, Wk, Wv, L0, L1, L2, L3, L4, L5);

    // 4) projections on tensor cores
    tc_gemm<<<(NN + 127) / 128, 256, TC_SMEM>>>(node_emb, NN,
        0, 0, Wq, bq, p_q,
        -1, 0, nullptr, nullptr, nullptr,
        -1, 0, nullptr, nullptr, nullptr);
    tc_gemm<<<(GG + 127) / 128, 256, TC_SMEM>>>(group_emb, GG,
        1, 0, Wk, bk, p_k,
        2, 0, Wv, bv, p_val,
        -1, 0, nullptr, nullptr, nullptr);

    // 5) per-group layer-1 factorization tables
    pprep_kernel<<<(GG * 512 + 255) / 256, 256>>>(Wp1, Ws1);

    // 6) fused edge pipeline (group-sorted order)
    edge_kernel<<<304, 256, EDGE_SMEM>>>(node_idx, group_idx, edge_attr, edge_vec,
                                         bp1, bs1, Wp2, bp2, Ws2, bs2, group_vec);

    // 7) node-side GEMMs: ms -> t0/t4/t5 ; node_vec -> dv (fused) / v1 / v2
    tc_gemm<<<(NN + 127) / 128, 256, TC_SMEM>>>(p_ms, NN,
        3, 0, L0, nullptr, p_t0,
        7, 0, L4, nullptr, p_t4,
        8, 0, L5, nullptr, p_t5);
    tc_gemm<<<(3 * NN + 127) / 128, 256, TC_SMEM>>>(node_vec, 3 * NN,
        4, 1, L1, nullptr, out_dv,
        5, 0, L2, nullptr, p_v1,
        6, 0, L3, nullptr, p_v2);

    // 8) finalize dx
    finalize_kernel<<<(NN * 32 + 255) / 256, 256>>>(out);
}